// round 13
// baseline (speedup 1.0000x reference)
#include <cuda_runtime.h>
#include <cstdint>

// Problem constants
#define D_DIM 4096
#define E_DIM 64
#define BM 128
#define BK 64
#define NTHREADS 256
#define KSTAGES (D_DIM / BK)   // 64
#define NSTAGE 3

// ---------------- smem layout (dynamic, bytes) ----------------
// per stage: A [128 rows][68 floats] (stride 68 -> conflict-free frag LDS; rows 256B data)
//            B frag-ordered tf32 [kk(8)][nb(8)][lane(32)][2]  (16KB contiguous)
#define A_STRIDE_F 68
#define A_ROW_BYTES (BK * 4)                    // 256
#define A_TILE_BYTES (BM * A_STRIDE_F * 4)      // 34816
#define B_TILE_BYTES (8 * 8 * 64 * 4)           // 16384
#define STAGE_BYTES (A_TILE_BYTES + B_TILE_BYTES)  // 51200
#define SMEM_TOTAL (NSTAGE * STAGE_BYTES)          // 153600
#define STAGE_TX (BM * A_ROW_BYTES + B_TILE_BYTES) // 49152
#define LS_STRIDE 65
#define TAU 4e-3f
#define FIX_CAP 16384

// W as tf32 (rna) in mma B-fragment order: [kb(512)][nb(8)][lane(32)][2]
__device__ float g_Wf[512 * 8 * 64];   // 1 MB
__device__ int   g_fix_count;
__device__ int   g_fix_rows[FIX_CAP];

__device__ __forceinline__ uint32_t cvt_tf32_u(float v) {
    uint32_t r;
    asm("cvt.rna.tf32.f32 %0, %1;" : "=r"(r) : "f"(v));
    return r;
}
__device__ __forceinline__ uint32_t smem_u32(const void* p) {
    uint32_t a;
    asm("{ .reg .u64 t; cvta.to.shared.u64 t, %1; cvt.u32.u64 %0, t; }" : "=r"(a) : "l"(p));
    return a;
}
__device__ __forceinline__ void bulk_g2s(uint32_t dst, const void* src, uint32_t bytes, uint32_t mbar) {
    asm volatile(
        "cp.async.bulk.shared::cluster.global.mbarrier::complete_tx::bytes [%0], [%1], %2, [%3];"
        :: "r"(dst), "l"(src), "r"(bytes), "r"(mbar) : "memory");
}
__device__ __forceinline__ void mbar_init(uint32_t bar, uint32_t cnt) {
    asm volatile("mbarrier.init.shared.b64 [%0], %1;" :: "r"(bar), "r"(cnt) : "memory");
}
__device__ __forceinline__ void mbar_arrive(uint32_t bar) {
    asm volatile("mbarrier.arrive.shared.b64 _, [%0];" :: "r"(bar) : "memory");
}
__device__ __forceinline__ void mbar_arrive_tx(uint32_t bar, uint32_t tx) {
    asm volatile("mbarrier.arrive.expect_tx.shared.b64 _, [%0], %1;" :: "r"(bar), "r"(tx) : "memory");
}
__device__ __forceinline__ void mbar_wait(uint32_t bar, uint32_t parity) {
    asm volatile(
        "{\n\t.reg .pred P;\n"
        "W_%=:\n\t"
        "mbarrier.try_wait.parity.acquire.cta.shared::cta.b64 P, [%0], %1, 0x989680;\n\t"
        "@P bra D_%=;\n\t"
        "bra W_%=;\n"
        "D_%=:\n\t}"
        :: "r"(bar), "r"(parity) : "memory");
}
__device__ __forceinline__ bool better(float v, int i, float w, int j) {
    return (v > w) || (v == w && i < j);
}

#define MMA_TF32(C, A, b0, b1)                                              \
    asm volatile("mma.sync.aligned.m16n8k8.row.col.f32.tf32.tf32.f32 "      \
                 "{%0,%1,%2,%3}, {%4,%5,%6,%7}, {%8,%9}, {%0,%1,%2,%3};"    \
                 : "+f"((C)[0]), "+f"((C)[1]), "+f"((C)[2]), "+f"((C)[3])   \
                 : "r"((A)[0]), "r"((A)[1]), "r"((A)[2]), "r"((A)[3]),      \
                   "r"(b0), "r"(b1))

// ---------------- prep: W -> tf32 B-fragments; reset fixup counter ----------------
__global__ void prep_w_kernel(const float* __restrict__ W) {
    const int idx = blockIdx.x * blockDim.x + threadIdx.x;   // 0 .. 131071
    if (idx == 0) g_fix_count = 0;
    if (idx >= 512 * 8 * 32) return;
    const int lane = idx & 31;
    const int nb   = (idx >> 5) & 7;
    const int kb   = idx >> 8;
    const int n = nb * 8 + (lane >> 2);
#pragma unroll
    for (int j = 0; j < 2; j++) {
        const int k = kb * 8 + (lane & 3) + j * 4;
        float w = W[(size_t)n * D_DIM + k];
        g_Wf[(size_t)idx * 2 + j] = __uint_as_float(cvt_tf32_u(w));
    }
}

// ---------------- main fused GEMM + top-2 gate (tf32 fast path) ----------------
__global__ __launch_bounds__(NTHREADS, 1)
void gate_mma_kernel(const float* __restrict__ x,
                     const float* __restrict__ bias,
                     float* __restrict__ out,
                     int N, int writeIdx)
{
    extern __shared__ __align__(16) char smem[];
    float* smemf = reinterpret_cast<float*>(smem);
    __shared__ __align__(8) unsigned long long mbar_full[NSTAGE];
    __shared__ float sbias[E_DIM];

    const int tid  = threadIdx.x;
    const int wid  = tid >> 5;
    const int lane = tid & 31;
    const int rowBase = blockIdx.x * BM;
    const uint32_t mb0 = smem_u32(&mbar_full[0]);

    if (tid < E_DIM) sbias[tid] = bias[tid];
    if (tid == 0) {
        for (int s = 0; s < NSTAGE; s++) mbar_init(mb0 + s * 8, NTHREADS);
    }
    __syncthreads();

    // 8 warps: mw 0..3 -> rows mw*32..+32, nw 0..1 -> cols nw*32..+32
    const int mw = wid >> 1;
    const int nw = wid & 1;
    const int qr = lane >> 2;    // 0..7
    const int qc = lane & 3;     // 0..3

    float acc[2][4][4];
#pragma unroll
    for (int mt = 0; mt < 2; mt++)
#pragma unroll
        for (int nt = 0; nt < 4; nt++)
#pragma unroll
            for (int i = 0; i < 4; i++) acc[mt][nt][i] = 0.0f;

    const float* xbase = x + (size_t)rowBase * D_DIM;
    const uint32_t smem_b = smem_u32(smem);

    // fill stage t: 128 A-row bulks (256B) + 1 B bulk (16KB); every thread arrives.
    auto fill = [&](int t) {
        const int s = t % NSTAGE;
        const uint32_t mbar = mb0 + s * 8;
        const uint32_t abuf = smem_b + s * STAGE_BYTES;
        const uint32_t bbuf = abuf + A_TILE_BYTES;
        if (tid < BM) {
            mbar_arrive_tx(mbar, A_ROW_BYTES);
            bulk_g2s(abuf + tid * (A_STRIDE_F * 4),
                     xbase + (size_t)tid * D_DIM + t * BK,
                     A_ROW_BYTES, mbar);
        } else if (tid == BM) {
            mbar_arrive_tx(mbar, B_TILE_BYTES);
            bulk_g2s(bbuf, g_Wf + (size_t)t * 4096, B_TILE_BYTES, mbar);
        } else {
            mbar_arrive(mbar);
        }
    };

    fill(0);
    fill(1);

    for (int t = 0; t < KSTAGES; t++) {
        if (t + 2 < KSTAGES) fill(t + 2);
        const int s = t % NSTAGE;
        mbar_wait(mb0 + s * 8, (t / NSTAGE) & 1);

        const float* As = smemf + (s * STAGE_BYTES) / 4;
        const float* Bs = As + A_TILE_BYTES / 4;

        // register software pipeline over kk (8 sub-steps of K=8)
        uint32_t af[2][2][4];
        float    bf[2][4][2];
        {
#pragma unroll
            for (int mt = 0; mt < 2; mt++) {
                const int r = mw * 32 + mt * 16 + qr;
                af[0][mt][0] = cvt_tf32_u(As[(r    ) * A_STRIDE_F + qc    ]);
                af[0][mt][1] = cvt_tf32_u(As[(r + 8) * A_STRIDE_F + qc    ]);
                af[0][mt][2] = cvt_tf32_u(As[(r    ) * A_STRIDE_F + qc + 4]);
                af[0][mt][3] = cvt_tf32_u(As[(r + 8) * A_STRIDE_F + qc + 4]);
            }
#pragma unroll
            for (int nt = 0; nt < 4; nt++) {
                const int nb = nw * 4 + nt;
                const float2 bfv = *reinterpret_cast<const float2*>(
                    Bs + ((0 * 8 + nb) * 64 + lane * 2));
                bf[0][nt][0] = bfv.x; bf[0][nt][1] = bfv.y;
            }
        }

#pragma unroll
        for (int kk = 0; kk < 8; kk++) {
            const int cur = kk & 1;
            const int nxt = cur ^ 1;
            if (kk < 7) {
                const int k0 = (kk + 1) * 8;
#pragma unroll
                for (int mt = 0; mt < 2; mt++) {
                    const int r = mw * 32 + mt * 16 + qr;
                    af[nxt][mt][0] = cvt_tf32_u(As[(r    ) * A_STRIDE_F + k0 + qc    ]);
                    af[nxt][mt][1] = cvt_tf32_u(As[(r + 8) * A_STRIDE_F + k0 + qc    ]);
                    af[nxt][mt][2] = cvt_tf32_u(As[(r    ) * A_STRIDE_F + k0 + qc + 4]);
                    af[nxt][mt][3] = cvt_tf32_u(As[(r + 8) * A_STRIDE_F + k0 + qc + 4]);
                }
#pragma unroll
                for (int nt = 0; nt < 4; nt++) {
                    const int nb = nw * 4 + nt;
                    const float2 bfv = *reinterpret_cast<const float2*>(
                        Bs + (((kk + 1) * 8 + nb) * 64 + lane * 2));
                    bf[nxt][nt][0] = bfv.x; bf[nxt][nt][1] = bfv.y;
                }
            }
#pragma unroll
            for (int nt = 0; nt < 4; nt++) {
                const uint32_t b0 = __float_as_uint(bf[cur][nt][0]);
                const uint32_t b1 = __float_as_uint(bf[cur][nt][1]);
                MMA_TF32(acc[0][nt], af[cur][0], b0, b1);
                MMA_TF32(acc[1][nt], af[cur][1], b0, b1);
            }
        }
        __syncthreads();   // all threads done with stage s before it is refilled
    }

    // ---- accumulators -> smem logits [128][65] ----
    float* Ls = smemf;
#pragma unroll
    for (int mt = 0; mt < 2; mt++) {
#pragma unroll
        for (int nt = 0; nt < 4; nt++) {
            const int r0 = mw * 32 + mt * 16 + qr;
            const int c0 = nw * 32 + nt * 8 + qc * 2;
            Ls[(r0    ) * LS_STRIDE + c0    ] = acc[mt][nt][0];
            Ls[(r0    ) * LS_STRIDE + c0 + 1] = acc[mt][nt][1];
            Ls[(r0 + 8) * LS_STRIDE + c0    ] = acc[mt][nt][2];
            Ls[(r0 + 8) * LS_STRIDE + c0 + 1] = acc[mt][nt][3];
        }
    }
    __syncthreads();

    // ---- top-3 + softmax + scatter + ambiguity flag: warps 0-3, row per lane ----
    if (wid < 4) {
        const int r = wid * 32 + lane;
        const float* lrow = Ls + r * LS_STRIDE;
        float v1 = -3.4e38f, v2 = -3.4e38f, v3 = -3.4e38f;
        int i1 = 0, i2 = 0, i3 = 0;
#pragma unroll
        for (int j = 0; j < E_DIM; j++) {
            float f = lrow[j] + sbias[j];
            if (better(f, j, v1, i1)) { v3 = v2; i3 = i2; v2 = v1; i2 = i1; v1 = f; i1 = j; }
            else if (better(f, j, v2, i2)) { v3 = v2; i3 = i2; v2 = f; i2 = j; }
            else if (better(f, j, v3, i3)) { v3 = f; i3 = j; }
        }
        float e  = expf(v2 - v1);
        float p1 = 1.0f / (1.0f + e);
        float p2 = e * p1;

        const int grow = rowBase + r;
        float* orow = out + (size_t)grow * E_DIM;
#pragma unroll
        for (int jj = 0; jj < 16; jj++) {
            float4 v;
            const int j0 = jj * 4;
            v.x = (j0     == i1) ? p1 : ((j0     == i2) ? p2 : 0.0f);
            v.y = (j0 + 1 == i1) ? p1 : ((j0 + 1 == i2) ? p2 : 0.0f);
            v.z = (j0 + 2 == i1) ? p1 : ((j0 + 2 == i2) ? p2 : 0.0f);
            v.w = (j0 + 3 == i1) ? p1 : ((j0 + 3 == i2) ? p2 : 0.0f);
            *reinterpret_cast<float4*>(orow + j0) = v;
        }
        if (writeIdx) {
            float2 ix = make_float2((float)i1, (float)i2);
            *reinterpret_cast<float2*>(out + (size_t)N * E_DIM + (size_t)grow * 2) = ix;
        }
        // ambiguous ordering? -> exact fixup
        if ((v1 - v2 < TAU) || (v2 - v3 < TAU)) {
            int pos = atomicAdd(&g_fix_count, 1);
            if (pos < FIX_CAP) g_fix_rows[pos] = grow;
        }
    }
}

// ---------------- fixup: exact fp32 recompute of flagged rows ----------------
__global__ __launch_bounds__(256)
void fix_kernel(const float* __restrict__ x,
                const float* __restrict__ W,
                const float* __restrict__ bias,
                float* __restrict__ out,
                int N, int writeIdx)
{
    __shared__ float4 sx[D_DIM / 4];     // 16 KB
    __shared__ float  sl[E_DIM];
    __shared__ float  sp1, sp2;
    __shared__ int    si1, si2;

    const int tid  = threadIdx.x;
    const int wid  = tid >> 5;
    const int lane = tid & 31;
    const int cnt = min(g_fix_count, FIX_CAP);

    for (int i = blockIdx.x; i < cnt; i += gridDim.x) {
        const int row = g_fix_rows[i];
        const float4* xrow = reinterpret_cast<const float4*>(x + (size_t)row * D_DIM);
        for (int j = tid; j < D_DIM / 4; j += 256) sx[j] = xrow[j];
        __syncthreads();

        for (int e = wid; e < E_DIM; e += 8) {
            const float4* wrow = reinterpret_cast<const float4*>(W + (size_t)e * D_DIM);
            float s = 0.0f;
#pragma unroll 8
            for (int q = 0; q < D_DIM / 4 / 32; q++) {
                float4 a = sx[lane + q * 32];
                float4 b = __ldg(&wrow[lane + q * 32]);
                s += a.x * b.x + a.y * b.y + a.z * b.z + a.w * b.w;
            }
#pragma unroll
            for (int off = 16; off > 0; off >>= 1)
                s += __shfl_xor_sync(0xffffffffu, s, off);
            if (lane == 0) sl[e] = s + bias[e];
        }
        __syncthreads();

        if (tid == 0) {
            float v1 = -3.4e38f, v2 = -3.4e38f;
            int i1 = 0, i2 = 0;
            for (int j = 0; j < E_DIM; j++) {
                float f = sl[j];
                if (better(f, j, v1, i1)) { v2 = v1; i2 = i1; v1 = f; i1 = j; }
                else if (better(f, j, v2, i2)) { v2 = f; i2 = j; }
            }
            float e2 = expf(v2 - v1);
            float p1 = 1.0f / (1.0f + e2);
            sp1 = p1; sp2 = e2 * p1; si1 = i1; si2 = i2;
        }
        __syncthreads();

        if (tid < E_DIM) {
            float g = (tid == si1) ? sp1 : ((tid == si2) ? sp2 : 0.0f);
            out[(size_t)row * E_DIM + tid] = g;
        }
        if (writeIdx && tid == 0) {
            float* oi = out + (size_t)N * E_DIM;
            oi[(size_t)row * 2 + 0] = (float)si1;
            oi[(size_t)row * 2 + 1] = (float)si2;
        }
        __syncthreads();
    }
}

extern "C" void kernel_launch(void* const* d_in, const int* in_sizes, int n_in,
                              void* d_out, int out_size)
{
    const float* x  = (const float*)d_in[0];
    const float* Wm = (const float*)d_in[1];
    const float* b  = (const float*)d_in[2];
    float* out = (float*)d_out;

    const int N = in_sizes[0] / D_DIM;   // 16384
    const int writeIdx = (out_size >= N * E_DIM + 2 * N) ? 1 : 0;

    cudaFuncSetAttribute(gate_mma_kernel,
                         cudaFuncAttributeMaxDynamicSharedMemorySize, SMEM_TOTAL);

    prep_w_kernel<<<512, 256>>>(Wm);
    gate_mma_kernel<<<N / BM, NTHREADS, SMEM_TOTAL>>>(x, b, out, N, writeIdx);
    fix_kernel<<<512, 256>>>(x, Wm, b, out, N, writeIdx);
}

// round 14
// speedup vs baseline: 1.3752x; 1.3752x over previous
#include <cuda_runtime.h>
#include <cuda_fp16.h>
#include <cstdint>

// Problem constants
#define D_DIM 4096
#define E_DIM 64
#define BM 128
#define BK 64
#define NTHREADS 256
#define KSTAGES (D_DIM / BK)   // 64
#define NSTAGE 3

// ---------------- smem layout (dynamic, bytes) ----------------
// per stage: A [128 rows][72 floats] fp32 (stride 72 -> conflict-free float2 frag LDS)
//            B fp16 frag-ordered [kk(4)][nb(8)][lane(32)][2]u32  (8KB)
#define A_STRIDE_F 72
#define A_TILE_BYTES (BM * A_STRIDE_F * 4)      // 36864
#define B_TILE_BYTES (4 * 8 * 32 * 2 * 4)       // 8192
#define STAGE_BYTES (A_TILE_BYTES + B_TILE_BYTES)  // 45056
#define SMEM_TOTAL (NSTAGE * STAGE_BYTES)          // 135168
#define LS_STRIDE 65
#define TAU 4e-3f
#define FIX_CAP 16384

// W as fp16 in mma m16n8k16 B-fragment order:
// g_Wh[kb16(256)][nb(8)][lane(32)][2] u32  (each u32 = f16x2)
__device__ uint32_t g_Wh[256 * 8 * 32 * 2];   // 512 KB
__device__ int      g_fix_count;
__device__ int      g_fix_rows[FIX_CAP];

__device__ __forceinline__ void cp_async16(void* dst, const void* src) {
    uint32_t d;
    asm("{ .reg .u64 t; cvta.to.shared.u64 t, %1; cvt.u32.u64 %0, t; }" : "=r"(d) : "l"(dst));
    asm volatile("cp.async.cg.shared.global [%0], [%1], 16;" :: "r"(d), "l"(src) : "memory");
}
__device__ __forceinline__ bool better(float v, int i, float w, int j) {
    return (v > w) || (v == w && i < j);
}
__device__ __forceinline__ uint32_t pack_h2(float lo, float hi) {
    uint32_t r;
    asm("cvt.rn.f16x2.f32 %0, %1, %2;" : "=r"(r) : "f"(hi), "f"(lo));
    return r;
}

#define MMA_F16(C, A, b0, b1)                                               \
    asm volatile("mma.sync.aligned.m16n8k16.row.col.f32.f16.f16.f32 "       \
                 "{%0,%1,%2,%3}, {%4,%5,%6,%7}, {%8,%9}, {%0,%1,%2,%3};"    \
                 : "+f"((C)[0]), "+f"((C)[1]), "+f"((C)[2]), "+f"((C)[3])   \
                 : "r"((A)[0]), "r"((A)[1]), "r"((A)[2]), "r"((A)[3]),      \
                   "r"(b0), "r"(b1))

// ---------------- prep: W -> fp16 B-fragments; reset fixup counter ----------------
__global__ void prep_w_kernel(const float* __restrict__ W) {
    const int idx = blockIdx.x * blockDim.x + threadIdx.x;   // 0 .. 65535
    if (idx == 0) g_fix_count = 0;
    if (idx >= 256 * 8 * 32) return;
    const int lane = idx & 31;
    const int nb   = (idx >> 5) & 7;
    const int kb   = idx >> 8;          // 0..255
    const int n  = nb * 8 + (lane >> 2);
    const int k0 = kb * 16 + 2 * (lane & 3);
    const float* wr = W + (size_t)n * D_DIM;
    g_Wh[(size_t)idx * 2 + 0] = pack_h2(wr[k0    ], wr[k0 + 1]);
    g_Wh[(size_t)idx * 2 + 1] = pack_h2(wr[k0 + 8], wr[k0 + 9]);
}

// ---------------- main fused GEMM + top-2 gate (fp16 fast path) ----------------
__global__ __launch_bounds__(NTHREADS, 1)
void gate_mma_kernel(const float* __restrict__ x,
                     const float* __restrict__ bias,
                     float* __restrict__ out,
                     int N, int writeIdx)
{
    extern __shared__ __align__(16) char smem[];
    float* smemf = reinterpret_cast<float*>(smem);
    __shared__ float sbias[E_DIM];

    const int tid  = threadIdx.x;
    const int wid  = tid >> 5;
    const int lane = tid & 31;
    const int rowBase = blockIdx.x * BM;

    if (tid < E_DIM) sbias[tid] = bias[tid];

    // 8 warps: mw 0..3 -> rows mw*32..+32, nw 0..1 -> cols nw*32..+32
    const int mw = wid >> 1;
    const int nw = wid & 1;
    const int qr = lane >> 2;    // 0..7
    const int qc = lane & 3;     // 0..3

    float acc[2][4][4];
#pragma unroll
    for (int mt = 0; mt < 2; mt++)
#pragma unroll
        for (int nt = 0; nt < 4; nt++)
#pragma unroll
            for (int i = 0; i < 4; i++) acc[mt][nt][i] = 0.0f;

    const float* xbase = x + (size_t)rowBase * D_DIM;

    auto load_stage = [&](int t) {
        const int s = t % NSTAGE;
        char* abuf = smem + s * STAGE_BYTES;
        char* bbuf = abuf + A_TILE_BYTES;
        const int kb0 = t * BK;
        const uint32_t* bsrc = g_Wh + (size_t)t * 2048;
#pragma unroll
        for (int i = 0; i < 8; i++) {           // A: 2048 16B granules
            const int g = tid + i * 256;
            const int r = g >> 4, k4 = g & 15;
            cp_async16(abuf + r * (A_STRIDE_F * 4) + k4 * 16,
                       xbase + (size_t)r * D_DIM + kb0 + k4 * 4);
        }
#pragma unroll
        for (int i = 0; i < 2; i++) {           // B: 512 16B granules
            const int g = tid + i * 256;
            cp_async16(bbuf + g * 16, bsrc + g * 4);
        }
        asm volatile("cp.async.commit_group;" ::: "memory");
    };

    load_stage(0);
    load_stage(1);

    for (int t = 0; t < KSTAGES; t++) {
        if (t + 2 < KSTAGES) {
            load_stage(t + 2);
            asm volatile("cp.async.wait_group 2;" ::: "memory");
        } else if (t + 1 < KSTAGES) {
            asm volatile("cp.async.wait_group 1;" ::: "memory");
        } else {
            asm volatile("cp.async.wait_group 0;" ::: "memory");
        }
        __syncthreads();

        const int s = t % NSTAGE;
        const float* As = smemf + (s * STAGE_BYTES) / 4;
        const float* Bs = As + A_TILE_BYTES / 4;   // B frag area as float words

#pragma unroll
        for (int kk = 0; kk < 4; kk++) {           // 4 k16 sub-steps
            const int k0 = kk * 16 + 2 * qc;
            uint32_t af[2][4];
#pragma unroll
            for (int mt = 0; mt < 2; mt++) {
                const int r = mw * 32 + mt * 16 + qr;
                const float2 v0 = *reinterpret_cast<const float2*>(&As[(r    ) * A_STRIDE_F + k0    ]);
                const float2 v1 = *reinterpret_cast<const float2*>(&As[(r + 8) * A_STRIDE_F + k0    ]);
                const float2 v2 = *reinterpret_cast<const float2*>(&As[(r    ) * A_STRIDE_F + k0 + 8]);
                const float2 v3 = *reinterpret_cast<const float2*>(&As[(r + 8) * A_STRIDE_F + k0 + 8]);
                af[mt][0] = pack_h2(v0.x, v0.y);
                af[mt][1] = pack_h2(v1.x, v1.y);
                af[mt][2] = pack_h2(v2.x, v2.y);
                af[mt][3] = pack_h2(v3.x, v3.y);
            }
#pragma unroll
            for (int nt = 0; nt < 4; nt++) {
                const int nb = nw * 4 + nt;
                const float2 bfv = *reinterpret_cast<const float2*>(
                    Bs + ((kk * 8 + nb) * 32 + lane) * 2);
                const uint32_t b0 = __float_as_uint(bfv.x);
                const uint32_t b1 = __float_as_uint(bfv.y);
                MMA_F16(acc[0][nt], af[0], b0, b1);
                MMA_F16(acc[1][nt], af[1], b0, b1);
            }
        }
    }
    __syncthreads();

    // ---- accumulators -> smem logits [128][65] ----
    float* Ls = smemf;
#pragma unroll
    for (int mt = 0; mt < 2; mt++) {
#pragma unroll
        for (int nt = 0; nt < 4; nt++) {
            const int r0 = mw * 32 + mt * 16 + qr;
            const int c0 = nw * 32 + nt * 8 + qc * 2;
            Ls[(r0    ) * LS_STRIDE + c0    ] = acc[mt][nt][0];
            Ls[(r0    ) * LS_STRIDE + c0 + 1] = acc[mt][nt][1];
            Ls[(r0 + 8) * LS_STRIDE + c0    ] = acc[mt][nt][2];
            Ls[(r0 + 8) * LS_STRIDE + c0 + 1] = acc[mt][nt][3];
        }
    }
    __syncthreads();

    // ---- top-3 + softmax + scatter + ambiguity flag: warps 0-3, row per lane ----
    if (wid < 4) {
        const int r = wid * 32 + lane;
        const float* lrow = Ls + r * LS_STRIDE;
        float v1 = -3.4e38f, v2 = -3.4e38f, v3 = -3.4e38f;
        int i1 = 0, i2 = 0, i3 = 0;
#pragma unroll
        for (int j = 0; j < E_DIM; j++) {
            float f = lrow[j] + sbias[j];
            if (better(f, j, v1, i1)) { v3 = v2; i3 = i2; v2 = v1; i2 = i1; v1 = f; i1 = j; }
            else if (better(f, j, v2, i2)) { v3 = v2; i3 = i2; v2 = f; i2 = j; }
            else if (better(f, j, v3, i3)) { v3 = f; i3 = j; }
        }
        float e  = expf(v2 - v1);
        float p1 = 1.0f / (1.0f + e);
        float p2 = e * p1;

        const int grow = rowBase + r;
        float* orow = out + (size_t)grow * E_DIM;
#pragma unroll
        for (int jj = 0; jj < 16; jj++) {
            float4 v;
            const int j0 = jj * 4;
            v.x = (j0     == i1) ? p1 : ((j0     == i2) ? p2 : 0.0f);
            v.y = (j0 + 1 == i1) ? p1 : ((j0 + 1 == i2) ? p2 : 0.0f);
            v.z = (j0 + 2 == i1) ? p1 : ((j0 + 2 == i2) ? p2 : 0.0f);
            v.w = (j0 + 3 == i1) ? p1 : ((j0 + 3 == i2) ? p2 : 0.0f);
            *reinterpret_cast<float4*>(orow + j0) = v;
        }
        if (writeIdx) {
            float2 ix = make_float2((float)i1, (float)i2);
            *reinterpret_cast<float2*>(out + (size_t)N * E_DIM + (size_t)grow * 2) = ix;
        }
        // ambiguous ordering? -> exact fixup
        if ((v1 - v2 < TAU) || (v2 - v3 < TAU)) {
            int pos = atomicAdd(&g_fix_count, 1);
            if (pos < FIX_CAP) g_fix_rows[pos] = grow;
        }
    }
}

// ---------------- fixup: exact fp32 recompute of flagged rows ----------------
__global__ __launch_bounds__(256)
void fix_kernel(const float* __restrict__ x,
                const float* __restrict__ W,
                const float* __restrict__ bias,
                float* __restrict__ out,
                int N, int writeIdx)
{
    __shared__ float4 sx[D_DIM / 4];     // 16 KB
    __shared__ float  sl[E_DIM];
    __shared__ float  sp1, sp2;
    __shared__ int    si1, si2;

    const int tid  = threadIdx.x;
    const int wid  = tid >> 5;
    const int lane = tid & 31;
    const int cnt = min(g_fix_count, FIX_CAP);

    for (int i = blockIdx.x; i < cnt; i += gridDim.x) {
        const int row = g_fix_rows[i];
        const float4* xrow = reinterpret_cast<const float4*>(x + (size_t)row * D_DIM);
        for (int j = tid; j < D_DIM / 4; j += 256) sx[j] = xrow[j];
        __syncthreads();

        for (int e = wid; e < E_DIM; e += 8) {
            const float4* wrow = reinterpret_cast<const float4*>(W + (size_t)e * D_DIM);
            float s = 0.0f;
#pragma unroll 8
            for (int q = 0; q < D_DIM / 4 / 32; q++) {
                float4 a = sx[lane + q * 32];
                float4 b = __ldg(&wrow[lane + q * 32]);
                s += a.x * b.x + a.y * b.y + a.z * b.z + a.w * b.w;
            }
#pragma unroll
            for (int off = 16; off > 0; off >>= 1)
                s += __shfl_xor_sync(0xffffffffu, s, off);
            if (lane == 0) sl[e] = s + bias[e];
        }
        __syncthreads();

        if (tid == 0) {
            float v1 = -3.4e38f, v2 = -3.4e38f;
            int i1 = 0, i2 = 0;
            for (int j = 0; j < E_DIM; j++) {
                float f = sl[j];
                if (better(f, j, v1, i1)) { v2 = v1; i2 = i1; v1 = f; i1 = j; }
                else if (better(f, j, v2, i2)) { v2 = f; i2 = j; }
            }
            float e2 = expf(v2 - v1);
            float p1 = 1.0f / (1.0f + e2);
            sp1 = p1; sp2 = e2 * p1; si1 = i1; si2 = i2;
        }
        __syncthreads();

        if (tid < E_DIM) {
            float g = (tid == si1) ? sp1 : ((tid == si2) ? sp2 : 0.0f);
            out[(size_t)row * E_DIM + tid] = g;
        }
        if (writeIdx && tid == 0) {
            float* oi = out + (size_t)N * E_DIM;
            oi[(size_t)row * 2 + 0] = (float)si1;
            oi[(size_t)row * 2 + 1] = (float)si2;
        }
        __syncthreads();
    }
}

extern "C" void kernel_launch(void* const* d_in, const int* in_sizes, int n_in,
                              void* d_out, int out_size)
{
    const float* x  = (const float*)d_in[0];
    const float* Wm = (const float*)d_in[1];
    const float* b  = (const float*)d_in[2];
    float* out = (float*)d_out;

    const int N = in_sizes[0] / D_DIM;   // 16384
    const int writeIdx = (out_size >= N * E_DIM + 2 * N) ? 1 : 0;

    cudaFuncSetAttribute(gate_mma_kernel,
                         cudaFuncAttributeMaxDynamicSharedMemorySize, SMEM_TOTAL);

    prep_w_kernel<<<256, 256>>>(Wm);
    gate_mma_kernel<<<N / BM, NTHREADS, SMEM_TOTAL>>>(x, b, out, N, writeIdx);
    fix_kernel<<<512, 256>>>(x, Wm, b, out, N, writeIdx);
}